// round 1
// baseline (speedup 1.0000x reference)
#include <cuda_runtime.h>
#include <math.h>

// Problem constants (fixed by the reference)
#define NN     200000
#define KK     16
#define GG     4000
#define NPG    50        // nodes per graph
#define F1     25        // F_IN
#define H1     16
#define H2     8
#define OUTC   2
#define EPS    1e-5f

// ---------------- scratch (device globals; no allocation allowed) ----------------
__device__ float g_A1[NN * F1];
__device__ float g_B1[NN * F1];
__device__ float g_h1[NN * H1];
__device__ float g_A2[NN * H1];
__device__ float g_B2[NN * H1];
__device__ float g_h2[NN * H2];

__device__ float g_W1[H1 * 4 * F1];   // 16 x 100 folded (post blocks summed, lin folded)
__device__ float g_bias1[H1];
__device__ float g_W2[H2 * 4 * H1];   // 8 x 64
__device__ float g_bias2[H2];

// ---------------- kernel 0: fold weights ----------------
// out = agg@w_post.T + b_post ; out = out@w_lin.T + b_lin, with the 3 degree-scaler
// copies identical => effective W = w_lin @ (w_post[:,0:4F] + w_post[:,4F:8F] + w_post[:,8F:12F])
__global__ void fold_kernel(const float* __restrict__ w1_post, const float* __restrict__ b1_post,
                            const float* __restrict__ w1_lin,  const float* __restrict__ b1_lin,
                            const float* __restrict__ w2_post, const float* __restrict__ b2_post,
                            const float* __restrict__ w2_lin,  const float* __restrict__ b2_lin)
{
    int t = threadIdx.x;
    // W1: [16,100], w1_post: [16, 300], w1_lin: [16,16]
    for (int idx = t; idx < H1 * 4 * F1; idx += blockDim.x) {
        int o = idx / (4 * F1), j = idx % (4 * F1);
        float s = 0.f;
        for (int k = 0; k < H1; k++) {
            float wp = w1_post[k * (12 * F1) + j]
                     + w1_post[k * (12 * F1) + 4 * F1 + j]
                     + w1_post[k * (12 * F1) + 8 * F1 + j];
            s += w1_lin[o * H1 + k] * wp;
        }
        g_W1[idx] = s;
    }
    for (int idx = t; idx < H1; idx += blockDim.x) {
        float s = b1_lin[idx];
        for (int k = 0; k < H1; k++) s += w1_lin[idx * H1 + k] * b1_post[k];
        g_bias1[idx] = s;
    }
    // W2: [8,64], w2_post: [8,192], w2_lin: [8,8]
    for (int idx = t; idx < H2 * 4 * H1; idx += blockDim.x) {
        int o = idx / (4 * H1), j = idx % (4 * H1);
        float s = 0.f;
        for (int k = 0; k < H2; k++) {
            float wp = w2_post[k * (12 * H1) + j]
                     + w2_post[k * (12 * H1) + 4 * H1 + j]
                     + w2_post[k * (12 * H1) + 8 * H1 + j];
            s += w2_lin[o * H2 + k] * wp;
        }
        g_W2[idx] = s;
    }
    for (int idx = t; idx < H2; idx += blockDim.x) {
        float s = b2_lin[idx];
        for (int k = 0; k < H2; k++) s += w2_lin[idx * H2 + k] * b2_post[k];
        g_bias2[idx] = s;
    }
}

// ---------------- kernel 1: per-node A1/B1 ----------------
// A1[n,f] = sum_i x[n,i]*w1_pre[f,i]      + b1_pre[f]   (dst half)
// B1[n,f] = sum_i x[n,i]*w1_pre[f,25+i]                  (src half)
__global__ void ab1_kernel(const float* __restrict__ x,
                           const float* __restrict__ w1_pre,
                           const float* __restrict__ b1_pre)
{
    int idx = blockIdx.x * blockDim.x + threadIdx.x;
    if (idx >= NN * F1) return;
    int n = idx / F1, f = idx % F1;
    const float* xr = x + n * F1;
    const float* w  = w1_pre + f * (2 * F1);
    float a = b1_pre[f], b = 0.f;
#pragma unroll
    for (int i = 0; i < F1; i++) {
        float xv = __ldg(xr + i);
        a = fmaf(xv, w[i], a);
        b = fmaf(xv, w[F1 + i], b);
    }
    g_A1[idx] = a;
    g_B1[idx] = b;
}

// ---------------- kernel 2: conv layer 1 (warp per node) ----------------
__global__ void conv1_kernel(const int* __restrict__ src)
{
    int gw   = (blockIdx.x * blockDim.x + threadIdx.x) >> 5;
    int lane = threadIdx.x & 31;
    int wslot = threadIdx.x >> 5;
    __shared__ float sh_agg[8][4 * F1 + 4];
    if (gw >= NN) return;
    int n = gw;

    if (lane < F1) {
        const int* sp = src + n * KK;
        float sum = 0.f, sumsq = 0.f, mn = 1e30f, mx = -1e30f;
#pragma unroll
        for (int e = 0; e < KK; e++) {
            int s = __ldg(sp + e);
            float b = __ldg(&g_B1[s * F1 + lane]);
            sum += b; sumsq = fmaf(b, b, sumsq);
            mn = fminf(mn, b); mx = fmaxf(mx, b);
        }
        float mean  = sum   * (1.f / KK);
        float mean2 = sumsq * (1.f / KK);
        float var   = mean2 - mean * mean;
        float stdv  = sqrtf(fmaxf(var, 0.f) + EPS);
        float A = g_A1[n * F1 + lane];
        sh_agg[wslot][lane]          = A + mean;
        sh_agg[wslot][F1 + lane]     = A + mn;
        sh_agg[wslot][2 * F1 + lane] = A + mx;
        sh_agg[wslot][3 * F1 + lane] = stdv;
    }
    __syncwarp();
    if (lane < H1) {
        float acc = g_bias1[lane];
        const float* w = g_W1 + lane * (4 * F1);
#pragma unroll
        for (int j = 0; j < 4 * F1; j++) acc = fmaf(w[j], sh_agg[wslot][j], acc);
        g_h1[n * H1 + lane] = fmaxf(acc, 0.f);
    }
}

// ---------------- kernel 3: per-node A2/B2 ----------------
__global__ void ab2_kernel(const float* __restrict__ w2_pre,
                           const float* __restrict__ b2_pre)
{
    int idx = blockIdx.x * blockDim.x + threadIdx.x;
    if (idx >= NN * H1) return;
    int n = idx >> 4, f = idx & 15;
    const float* hr = g_h1 + n * H1;
    const float* w  = w2_pre + f * (2 * H1);
    float a = b2_pre[f], b = 0.f;
#pragma unroll
    for (int i = 0; i < H1; i++) {
        float hv = hr[i];
        a = fmaf(hv, w[i], a);
        b = fmaf(hv, w[H1 + i], b);
    }
    g_A2[idx] = a;
    g_B2[idx] = b;
}

// ---------------- kernel 4: conv layer 2 (warp per node) ----------------
__global__ void conv2_kernel(const int* __restrict__ src)
{
    int gw   = (blockIdx.x * blockDim.x + threadIdx.x) >> 5;
    int lane = threadIdx.x & 31;
    int wslot = threadIdx.x >> 5;
    __shared__ float sh_agg[8][4 * H1 + 4];
    if (gw >= NN) return;
    int n = gw;

    if (lane < H1) {
        const int* sp = src + n * KK;
        float sum = 0.f, sumsq = 0.f, mn = 1e30f, mx = -1e30f;
#pragma unroll
        for (int e = 0; e < KK; e++) {
            int s = __ldg(sp + e);
            float b = __ldg(&g_B2[s * H1 + lane]);
            sum += b; sumsq = fmaf(b, b, sumsq);
            mn = fminf(mn, b); mx = fmaxf(mx, b);
        }
        float mean  = sum   * (1.f / KK);
        float mean2 = sumsq * (1.f / KK);
        float var   = mean2 - mean * mean;
        float stdv  = sqrtf(fmaxf(var, 0.f) + EPS);
        float A = g_A2[n * H1 + lane];
        sh_agg[wslot][lane]          = A + mean;
        sh_agg[wslot][H1 + lane]     = A + mn;
        sh_agg[wslot][2 * H1 + lane] = A + mx;
        sh_agg[wslot][3 * H1 + lane] = stdv;
    }
    __syncwarp();
    if (lane < H2) {
        float acc = g_bias2[lane];
        const float* w = g_W2 + lane * (4 * H1);
#pragma unroll
        for (int j = 0; j < 4 * H1; j++) acc = fmaf(w[j], sh_agg[wslot][j], acc);
        g_h2[n * H2 + lane] = fmaxf(acc, 0.f);
    }
}

// ---------------- kernel 5: pool + fc + log_softmax (warp per graph) ----------------
__global__ void pool_kernel(const float* __restrict__ fc_w,
                            const float* __restrict__ fc_b,
                            float* __restrict__ out)
{
    int gw   = (blockIdx.x * blockDim.x + threadIdx.x) >> 5;
    int lane = threadIdx.x & 31;
    if (gw >= GG) return;
    int g = gw;

    int f     = lane & 7;
    int group = lane >> 3;   // 0..3
    int base  = g * NPG;
    float acc = 0.f;
    for (int nn = group; nn < NPG; nn += 4)
        acc += g_h2[(base + nn) * H2 + f];
    // reduce across the 4 groups
    acc += __shfl_xor_sync(0xFFFFFFFFu, acc, 8);
    acc += __shfl_xor_sync(0xFFFFFFFFu, acc, 16);
    // lanes 0..7 now hold pooled[f]; broadcast to lane 0 via shuffles
    // compute both logits on lane 0
    float p = acc;  // valid for lane<8
    // gather pooled into lane 0 via warp shuffle reads
    float l0 = 0.f, l1 = 0.f;
#pragma unroll
    for (int j = 0; j < H2; j++) {
        float pj = __shfl_sync(0xFFFFFFFFu, p, j);
        if (lane == 0) {
            l0 = fmaf(pj, fc_w[0 * H2 + j], l0);
            l1 = fmaf(pj, fc_w[1 * H2 + j], l1);
        }
    }
    if (lane == 0) {
        l0 += fc_b[0];
        l1 += fc_b[1];
        float m   = fmaxf(l0, l1);
        float lse = m + logf(expf(l0 - m) + expf(l1 - m));
        out[g * OUTC + 0] = l0 - lse;
        out[g * OUTC + 1] = l1 - lse;
    }
}

// ---------------- launch ----------------
extern "C" void kernel_launch(void* const* d_in, const int* in_sizes, int n_in,
                              void* d_out, int out_size)
{
    // metadata order:
    // 0:x 1:edge_index 2:batch 3:w1_pre 4:b1_pre 5:w1_post 6:b1_post 7:w1_lin 8:b1_lin
    // 9:w2_pre 10:b2_pre 11:w2_post 12:b2_post 13:w2_lin 14:b2_lin 15:fc_w 16:fc_b
    const float* x       = (const float*)d_in[0];
    const int*   src     = (const int*)d_in[1];           // edge_index[0] = first E ints
    const float* w1_pre  = (const float*)d_in[3];
    const float* b1_pre  = (const float*)d_in[4];
    const float* w1_post = (const float*)d_in[5];
    const float* b1_post = (const float*)d_in[6];
    const float* w1_lin  = (const float*)d_in[7];
    const float* b1_lin  = (const float*)d_in[8];
    const float* w2_pre  = (const float*)d_in[9];
    const float* b2_pre  = (const float*)d_in[10];
    const float* w2_post = (const float*)d_in[11];
    const float* b2_post = (const float*)d_in[12];
    const float* w2_lin  = (const float*)d_in[13];
    const float* b2_lin  = (const float*)d_in[14];
    const float* fc_w    = (const float*)d_in[15];
    const float* fc_b    = (const float*)d_in[16];
    float* out = (float*)d_out;

    fold_kernel<<<1, 256>>>(w1_post, b1_post, w1_lin, b1_lin,
                            w2_post, b2_post, w2_lin, b2_lin);

    {
        int total = NN * F1;
        ab1_kernel<<<(total + 255) / 256, 256>>>(x, w1_pre, b1_pre);
    }
    {
        int nwarps = NN;                     // one warp per node
        int blocks = (nwarps + 7) / 8;       // 8 warps / 256-thread block
        conv1_kernel<<<blocks, 256>>>(src);
    }
    {
        int total = NN * H1;
        ab2_kernel<<<(total + 255) / 256, 256>>>(w2_pre, b2_pre);
    }
    {
        int nwarps = NN;
        int blocks = (nwarps + 7) / 8;
        conv2_kernel<<<blocks, 256>>>(src);
    }
    {
        int nwarps = GG;
        int blocks = (nwarps + 7) / 8;
        pool_kernel<<<blocks, 256>>>(fc_w, fc_b, out);
    }
}

// round 2
// speedup vs baseline: 4.2011x; 4.2011x over previous
#include <cuda_runtime.h>
#include <math.h>

#define NN     200000
#define KK     16
#define GG     4000
#define NPG    50
#define F1     25
#define H1     16
#define H2     8
#define OUTC   2
#define EPS    1e-5f

// ---------------- scratch (device globals) ----------------
__device__ float g_B1[NN * 32];      // src-half messages layer1, rows padded to 32 floats (128B aligned)
__device__ float g_D1[NN * H1];      // folded dst contribution + bias, layer1
__device__ float g_h1[NN * H1];
__device__ float g_B2[NN * H1];      // rows 16 floats = 64B
__device__ float g_D2[NN * H2];
__device__ float g_h2[NN * H2];

__device__ float g_W1v[H1 * 100];    // folded post*lin weights, layer1: [16][100] (mean|min|max|std blocks)
__device__ float g_C1[H1 * F1];      // (Wm+Wn+Wx) @ w1_pre_dst : [16][25]
__device__ float g_c01[H1];
__device__ float g_W2v[H2 * 64];     // [8][64]
__device__ float g_C2[H2 * H1];      // [8][16]
__device__ float g_c02[H2];

// ---------------- kernel 0: fold weights (single block) ----------------
__global__ void fold_kernel(const float* __restrict__ w1_pre, const float* __restrict__ b1_pre,
                            const float* __restrict__ w1_post, const float* __restrict__ b1_post,
                            const float* __restrict__ w1_lin,  const float* __restrict__ b1_lin,
                            const float* __restrict__ w2_pre, const float* __restrict__ b2_pre,
                            const float* __restrict__ w2_post, const float* __restrict__ b2_post,
                            const float* __restrict__ w2_lin,  const float* __restrict__ b2_lin)
{
    __shared__ float sWA1[H1 * F1];   // (Wm+Wn+Wx) layer1
    __shared__ float sWA2[H2 * H1];
    int t = threadIdx.x;

    // W1v[o][j] = sum_k w1_lin[o][k] * (w1_post[k][j] + w1_post[k][100+j] + w1_post[k][200+j])
    for (int idx = t; idx < H1 * 100; idx += blockDim.x) {
        int o = idx / 100, j = idx % 100;
        float s = 0.f;
        for (int k = 0; k < H1; k++) {
            float p = w1_post[k * 300 + j] + w1_post[k * 300 + 100 + j] + w1_post[k * 300 + 200 + j];
            s = fmaf(w1_lin[o * H1 + k], p, s);
        }
        g_W1v[idx] = s;
    }
    // W2v[o][j] = sum_k w2_lin[o][k] * (w2_post[k][j] + [+64] + [+128])
    for (int idx = t; idx < H2 * 64; idx += blockDim.x) {
        int o = idx / 64, j = idx % 64;
        float s = 0.f;
        for (int k = 0; k < H2; k++) {
            float p = w2_post[k * 192 + j] + w2_post[k * 192 + 64 + j] + w2_post[k * 192 + 128 + j];
            s = fmaf(w2_lin[o * H2 + k], p, s);
        }
        g_W2v[idx] = s;
    }
    __syncthreads();
    // WA = Wm + Wn + Wx
    for (int idx = t; idx < H1 * F1; idx += blockDim.x) {
        int o = idx / F1, j = idx % F1;
        sWA1[idx] = g_W1v[o * 100 + j] + g_W1v[o * 100 + 25 + j] + g_W1v[o * 100 + 50 + j];
    }
    for (int idx = t; idx < H2 * H1; idx += blockDim.x) {
        int o = idx / H1, j = idx % H1;
        sWA2[idx] = g_W2v[o * 64 + j] + g_W2v[o * 64 + 16 + j] + g_W2v[o * 64 + 32 + j];
    }
    __syncthreads();
    // C1[o][i] = sum_j WA1[o][j] * w1_pre[j][i]   (dst half: cols 0..24 of [25][50])
    for (int idx = t; idx < H1 * F1; idx += blockDim.x) {
        int o = idx / F1, i = idx % F1;
        float s = 0.f;
        for (int j = 0; j < F1; j++) s = fmaf(sWA1[o * F1 + j], w1_pre[j * 50 + i], s);
        g_C1[idx] = s;
    }
    for (int idx = t; idx < H1; idx += blockDim.x) {
        float s = b1_lin[idx];
        for (int k = 0; k < H1; k++) s = fmaf(w1_lin[idx * H1 + k], b1_post[k], s);
        for (int j = 0; j < F1; j++) s = fmaf(sWA1[idx * F1 + j], b1_pre[j], s);
        g_c01[idx] = s;
    }
    // C2[o][i] = sum_j WA2[o][j] * w2_pre[j][i]   (dst half: cols 0..15 of [16][32])
    for (int idx = t; idx < H2 * H1; idx += blockDim.x) {
        int o = idx / H1, i = idx % H1;
        float s = 0.f;
        for (int j = 0; j < H1; j++) s = fmaf(sWA2[o * H1 + j], w2_pre[j * 32 + i], s);
        g_C2[idx] = s;
    }
    for (int idx = t; idx < H2; idx += blockDim.x) {
        float s = b2_lin[idx];
        for (int k = 0; k < H2; k++) s = fmaf(w2_lin[idx * H2 + k], b2_post[k], s);
        for (int j = 0; j < H1; j++) s = fmaf(sWA2[idx * H1 + j], b2_pre[j], s);
        g_c02[idx] = s;
    }
}

// ---------------- kernel 1: B1/D1 per node (tiled, coalesced) ----------------
__global__ void ab1_kernel(const float* __restrict__ x, const float* __restrict__ w1_pre)
{
    __shared__ float xs[256 * F1];          // 25.6 KB, reused for output staging
    __shared__ float ws[F1 * F1];           // src-half weights [j][i]
    __shared__ float cs[H1 * F1];           // C1
    __shared__ float c0s[H1];
    int t = threadIdx.x;
    int base = blockIdx.x * 256;
    int nvalid = NN - base; if (nvalid > 256) nvalid = 256;

    for (int i = t; i < F1 * F1; i += 256) ws[i] = w1_pre[(i / F1) * 50 + F1 + (i % F1)];
    for (int i = t; i < H1 * F1; i += 256) cs[i] = g_C1[i];
    if (t < H1) c0s[t] = g_c01[t];
    for (int i = t; i < nvalid * F1; i += 256) xs[i] = x[base * F1 + i];
    __syncthreads();

    bool act = (t < nvalid);
    float xr[F1];
    float b[F1];
    float d[H1];
    if (act) {
#pragma unroll
        for (int i = 0; i < F1; i++) xr[i] = xs[t * F1 + i];
#pragma unroll
        for (int j = 0; j < F1; j++) {
            float s = 0.f;
#pragma unroll
            for (int i = 0; i < F1; i++) s = fmaf(xr[i], ws[j * F1 + i], s);
            b[j] = s;
        }
#pragma unroll
        for (int o = 0; o < H1; o++) {
            float s = c0s[o];
#pragma unroll
            for (int i = 0; i < F1; i++) s = fmaf(xr[i], cs[o * F1 + i], s);
            d[o] = s;
        }
    }
    __syncthreads();
    if (act) {
#pragma unroll
        for (int j = 0; j < F1; j++) xs[t * F1 + j] = b[j];
    }
    __syncthreads();
    for (int i = t; i < nvalid * 32; i += 256) {
        int node = i >> 5, c = i & 31;
        if (c < F1) g_B1[(base + node) * 32 + c] = xs[node * F1 + c];
    }
    __syncthreads();
    if (act) {
#pragma unroll
        for (int o = 0; o < H1; o++) xs[t * H1 + o] = d[o];
    }
    __syncthreads();
    for (int i = t; i < nvalid * H1; i += 256) g_D1[base * H1 + i] = xs[i];
}

// ---------------- kernel 2: conv layer 1 (warp per node) ----------------
__global__ void conv1_kernel(const int* __restrict__ src)
{
    __shared__ float sW[H1 * 100];        // 6.4 KB, row stride 100 floats (400B, 16B-aligned)
    __shared__ float sagg[8][104];        // 104*4=416B row, 16B-aligned
    int t = threadIdx.x;
    for (int i = t; i < H1 * 100; i += 256) sW[i] = g_W1v[i];
    __syncthreads();

    int w = t >> 5, lane = t & 31;
    int n = blockIdx.x * 8 + w;           // grid = 25000 exact

    int sv = 0;
    if (lane < KK) sv = __ldg(&src[n * KK + lane]);
    float sum = 0.f, ss = 0.f, mn = 1e30f, mx = -1e30f;
#pragma unroll
    for (int e = 0; e < KK; e++) {
        int s = __shfl_sync(0xFFFFFFFFu, sv, e);
        if (lane < F1) {
            float bv = __ldg(&g_B1[s * 32 + lane]);
            sum += bv; ss = fmaf(bv, bv, ss);
            mn = fminf(mn, bv); mx = fmaxf(mx, bv);
        }
    }
    if (lane < F1) {
        float mean  = sum * (1.f / KK);
        float mean2 = ss  * (1.f / KK);
        float var   = mean2 - mean * mean;
        float stdv  = sqrtf(fmaxf(var, 0.f) + EPS);
        sagg[w][lane]      = mean;
        sagg[w][25 + lane] = mn;
        sagg[w][50 + lane] = mx;
        sagg[w][75 + lane] = stdv;
    }
    __syncwarp();
    if (lane < H1) {
        float4 acc = make_float4(0.f, 0.f, 0.f, 0.f);
        const float4* wr = (const float4*)&sW[lane * 100];
        const float4* ar = (const float4*)&sagg[w][0];
#pragma unroll
        for (int j4 = 0; j4 < 25; j4++) {
            float4 wv = wr[j4];
            float4 av = ar[j4];
            acc.x = fmaf(wv.x, av.x, acc.x);
            acc.y = fmaf(wv.y, av.y, acc.y);
            acc.z = fmaf(wv.z, av.z, acc.z);
            acc.w = fmaf(wv.w, av.w, acc.w);
        }
        float out = acc.x + acc.y + acc.z + acc.w + __ldg(&g_D1[n * H1 + lane]);
        g_h1[n * H1 + lane] = fmaxf(out, 0.f);
    }
}

// ---------------- kernel 3: B2/D2 per node ----------------
__global__ void ab2_kernel(const float* __restrict__ w2_pre)
{
    __shared__ float xs[256 * 17];        // h1 tile, padded stride 17 (conflict-free)
    __shared__ float ws[H1 * H1];         // src-half [j][i]
    __shared__ float cs[H2 * H1];
    __shared__ float c0s[H2];
    int t = threadIdx.x;
    int base = blockIdx.x * 256;
    int nvalid = NN - base; if (nvalid > 256) nvalid = 256;

    for (int i = t; i < H1 * H1; i += 256) ws[i] = w2_pre[(i / H1) * 32 + H1 + (i % H1)];
    for (int i = t; i < H2 * H1; i += 256) cs[i] = g_C2[i];
    if (t < H2) c0s[t] = g_c02[t];
    for (int i = t; i < nvalid * H1; i += 256) xs[(i / H1) * 17 + (i % H1)] = g_h1[base * H1 + i];
    __syncthreads();

    bool act = (t < nvalid);
    float hr[H1], b[H1], d[H2];
    if (act) {
#pragma unroll
        for (int i = 0; i < H1; i++) hr[i] = xs[t * 17 + i];
#pragma unroll
        for (int j = 0; j < H1; j++) {
            float s = 0.f;
#pragma unroll
            for (int i = 0; i < H1; i++) s = fmaf(hr[i], ws[j * H1 + i], s);
            b[j] = s;
        }
#pragma unroll
        for (int o = 0; o < H2; o++) {
            float s = c0s[o];
#pragma unroll
            for (int i = 0; i < H1; i++) s = fmaf(hr[i], cs[o * H1 + i], s);
            d[o] = s;
        }
    }
    __syncthreads();
    if (act) {
#pragma unroll
        for (int j = 0; j < H1; j++) xs[t * 17 + j] = b[j];
    }
    __syncthreads();
    for (int i = t; i < nvalid * H1; i += 256) g_B2[base * H1 + i] = xs[(i / H1) * 17 + (i % H1)];
    __syncthreads();
    if (act) {
#pragma unroll
        for (int o = 0; o < H2; o++) xs[t * 9 + o] = d[o];
    }
    __syncthreads();
    for (int i = t; i < nvalid * H2; i += 256) g_D2[base * H2 + i] = xs[(i / H2) * 9 + (i % H2)];
}

// ---------------- kernel 4: conv layer 2 (warp per node) ----------------
__global__ void conv2_kernel(const int* __restrict__ src)
{
    __shared__ float sW[H2 * 76];         // row stride 76 floats (304B, 16B-aligned, conflict-free)
    __shared__ float sagg[8][72];         // 72*4=288B, 16B-aligned
    int t = threadIdx.x;
    for (int i = t; i < H2 * 64; i += 256) sW[(i / 64) * 76 + (i % 64)] = g_W2v[i];
    __syncthreads();

    int w = t >> 5, lane = t & 31;
    int n = blockIdx.x * 8 + w;

    int sv = 0;
    if (lane < KK) sv = __ldg(&src[n * KK + lane]);
    float sum = 0.f, ss = 0.f, mn = 1e30f, mx = -1e30f;
#pragma unroll
    for (int e = 0; e < KK; e++) {
        int s = __shfl_sync(0xFFFFFFFFu, sv, e);
        if (lane < H1) {
            float bv = __ldg(&g_B2[s * H1 + lane]);
            sum += bv; ss = fmaf(bv, bv, ss);
            mn = fminf(mn, bv); mx = fmaxf(mx, bv);
        }
    }
    if (lane < H1) {
        float mean  = sum * (1.f / KK);
        float mean2 = ss  * (1.f / KK);
        float var   = mean2 - mean * mean;
        float stdv  = sqrtf(fmaxf(var, 0.f) + EPS);
        sagg[w][lane]      = mean;
        sagg[w][16 + lane] = mn;
        sagg[w][32 + lane] = mx;
        sagg[w][48 + lane] = stdv;
    }
    __syncwarp();
    if (lane < H2) {
        float4 acc = make_float4(0.f, 0.f, 0.f, 0.f);
        const float4* wr = (const float4*)&sW[lane * 76];
        const float4* ar = (const float4*)&sagg[w][0];
#pragma unroll
        for (int j4 = 0; j4 < 16; j4++) {
            float4 wv = wr[j4];
            float4 av = ar[j4];
            acc.x = fmaf(wv.x, av.x, acc.x);
            acc.y = fmaf(wv.y, av.y, acc.y);
            acc.z = fmaf(wv.z, av.z, acc.z);
            acc.w = fmaf(wv.w, av.w, acc.w);
        }
        float out = acc.x + acc.y + acc.z + acc.w + __ldg(&g_D2[n * H2 + lane]);
        g_h2[n * H2 + lane] = fmaxf(out, 0.f);
    }
}

// ---------------- kernel 5: pool + fc + log_softmax (warp per graph) ----------------
__global__ void pool_kernel(const float* __restrict__ fc_w,
                            const float* __restrict__ fc_b,
                            float* __restrict__ out)
{
    int gw   = (blockIdx.x * blockDim.x + threadIdx.x) >> 5;
    int lane = threadIdx.x & 31;
    if (gw >= GG) return;
    int g = gw;

    int f     = lane & 7;
    int group = lane >> 3;
    int base  = g * NPG;
    float acc = 0.f;
    for (int nn = group; nn < NPG; nn += 4)
        acc += g_h2[(base + nn) * H2 + f];
    acc += __shfl_xor_sync(0xFFFFFFFFu, acc, 8);
    acc += __shfl_xor_sync(0xFFFFFFFFu, acc, 16);
    float p = acc;
    float l0 = 0.f, l1 = 0.f;
#pragma unroll
    for (int j = 0; j < H2; j++) {
        float pj = __shfl_sync(0xFFFFFFFFu, p, j);
        if (lane == 0) {
            l0 = fmaf(pj, fc_w[j], l0);
            l1 = fmaf(pj, fc_w[H2 + j], l1);
        }
    }
    if (lane == 0) {
        l0 += fc_b[0];
        l1 += fc_b[1];
        float m   = fmaxf(l0, l1);
        float lse = m + logf(expf(l0 - m) + expf(l1 - m));
        out[g * OUTC + 0] = l0 - lse;
        out[g * OUTC + 1] = l1 - lse;
    }
}

// ---------------- launch ----------------
extern "C" void kernel_launch(void* const* d_in, const int* in_sizes, int n_in,
                              void* d_out, int out_size)
{
    const float* x       = (const float*)d_in[0];
    const int*   src     = (const int*)d_in[1];
    const float* w1_pre  = (const float*)d_in[3];
    const float* b1_pre  = (const float*)d_in[4];
    const float* w1_post = (const float*)d_in[5];
    const float* b1_post = (const float*)d_in[6];
    const float* w1_lin  = (const float*)d_in[7];
    const float* b1_lin  = (const float*)d_in[8];
    const float* w2_pre  = (const float*)d_in[9];
    const float* b2_pre  = (const float*)d_in[10];
    const float* w2_post = (const float*)d_in[11];
    const float* b2_post = (const float*)d_in[12];
    const float* w2_lin  = (const float*)d_in[13];
    const float* b2_lin  = (const float*)d_in[14];
    const float* fc_w    = (const float*)d_in[15];
    const float* fc_b    = (const float*)d_in[16];
    float* out = (float*)d_out;

    fold_kernel<<<1, 256>>>(w1_pre, b1_pre, w1_post, b1_post, w1_lin, b1_lin,
                            w2_pre, b2_pre, w2_post, b2_post, w2_lin, b2_lin);
    ab1_kernel<<<(NN + 255) / 256, 256>>>(x, w1_pre);
    conv1_kernel<<<NN / 8, 256>>>(src);
    ab2_kernel<<<(NN + 255) / 256, 256>>>(w2_pre);
    conv2_kernel<<<NN / 8, 256>>>(src);
    pool_kernel<<<(GG * 32 + 255) / 256, 256>>>(fc_w, fc_b, out);
}

// round 3
// speedup vs baseline: 5.0433x; 1.2005x over previous
#include <cuda_runtime.h>
#include <math.h>

#define NN  200000
#define KK  16
#define GG  4000
#define NPG 50
#define F1  25
#define H1  16
#define H2  8
#define EPS 1e-5f

// ---------------- scratch ----------------
__device__ float g_B1[NN * 32];     // layer1 src-half messages, row stride 32 (128B line)
__device__ float g_D1[NN * H1];     // folded dst contribution layer1
__device__ float g_B2[NN * H1];     // layer2 src-half messages
__device__ float g_D2[NN * H2];     // folded dst contribution layer2
__device__ float g_pooled[GG * H2]; // graph pooling accumulators

// =================================================================
// kernel 1: ab1 — per-node B1 (25) and D1 (16); inline weight fold;
// also zeros g_pooled.
// =================================================================
__global__ void __launch_bounds__(256) ab1_kernel(
    const float* __restrict__ x,
    const float* __restrict__ w1_pre, const float* __restrict__ b1_pre,
    const float* __restrict__ w1_post, const float* __restrict__ b1_post,
    const float* __restrict__ w1_lin,  const float* __restrict__ b1_lin)
{
    __shared__ __align__(16) float xs[256 * 28];  // x tile, stride 28, cols 25-27 zero
    __shared__ __align__(16) float ws[25 * 28];   // src-half weights, padded
    __shared__ __align__(16) float cs[16 * 28];   // C1 = WA1 @ w1_pre_dst, padded
    __shared__ float pa[16 * 25];                 // p9
    __shared__ float pb[16 * 25];                 // WA1
    __shared__ float c0s[16];

    int t = threadIdx.x;
    int base = blockIdx.x * 256;
    int nvalid = NN - base; if (nvalid > 256) nvalid = 256;

    if (blockIdx.x < 125) g_pooled[blockIdx.x * 256 + t] = 0.f;

    // p9[k][jj] = sum over 9 (block,scaler) offsets of w1_post
    for (int i = t; i < 16 * 25; i += 256) {
        int k = i / 25, jj = i % 25;
        const float* pr = w1_post + k * 300;
        pa[i] = pr[jj] + pr[25 + jj] + pr[50 + jj]
              + pr[100 + jj] + pr[125 + jj] + pr[150 + jj]
              + pr[200 + jj] + pr[225 + jj] + pr[250 + jj];
    }
    __syncthreads();
    // WA1 = w1_lin @ p9
    for (int i = t; i < 16 * 25; i += 256) {
        int o = i / 25, jj = i % 25;
        float s = 0.f;
        for (int k = 0; k < 16; k++) s = fmaf(w1_lin[o * 16 + k], pa[k * 25 + jj], s);
        pb[i] = s;
    }
    __syncthreads();
    // C1 = WA1 @ w1_pre_dst (padded to 28)
    for (int i = t; i < 16 * 28; i += 256) {
        int o = i / 28, ii = i % 28;
        float s = 0.f;
        if (ii < 25) { for (int j = 0; j < 25; j++) s = fmaf(pb[o * 25 + j], w1_pre[j * 50 + ii], s); }
        cs[i] = s;
    }
    // src-half weights padded
    for (int i = t; i < 25 * 28; i += 256) {
        int j = i / 28, ii = i % 28;
        ws[i] = (ii < 25) ? w1_pre[j * 50 + 25 + ii] : 0.f;
    }
    if (t < 16) {
        float s = b1_lin[t];
        for (int k = 0; k < 16; k++) s = fmaf(w1_lin[t * 16 + k], b1_post[k], s);
        for (int j = 0; j < 25; j++) s = fmaf(pb[t * 25 + j], b1_pre[j], s);
        c0s[t] = s;
    }
    // stage x tile
    for (int i = t; i < nvalid * 25; i += 256) xs[(i / 25) * 28 + (i % 25)] = x[base * 25 + i];
    for (int i = t; i < nvalid * 3; i += 256) xs[(i / 3) * 28 + 25 + (i % 3)] = 0.f;
    __syncthreads();

    float b[25], d[16];
    bool act = (t < nvalid);
    if (act) {
        float4 xr[7];
        const float4* xp = (const float4*)&xs[t * 28];
#pragma unroll
        for (int i = 0; i < 7; i++) xr[i] = xp[i];
        const float4* wp = (const float4*)ws;
#pragma unroll
        for (int j = 0; j < 25; j++) {
            float4 a = make_float4(0.f, 0.f, 0.f, 0.f);
#pragma unroll
            for (int i = 0; i < 7; i++) {
                float4 w4 = wp[j * 7 + i];
                a.x = fmaf(w4.x, xr[i].x, a.x); a.y = fmaf(w4.y, xr[i].y, a.y);
                a.z = fmaf(w4.z, xr[i].z, a.z); a.w = fmaf(w4.w, xr[i].w, a.w);
            }
            b[j] = (a.x + a.y) + (a.z + a.w);
        }
        const float4* cp = (const float4*)cs;
#pragma unroll
        for (int o = 0; o < 16; o++) {
            float4 a = make_float4(0.f, 0.f, 0.f, 0.f);
#pragma unroll
            for (int i = 0; i < 7; i++) {
                float4 w4 = cp[o * 7 + i];
                a.x = fmaf(w4.x, xr[i].x, a.x); a.y = fmaf(w4.y, xr[i].y, a.y);
                a.z = fmaf(w4.z, xr[i].z, a.z); a.w = fmaf(w4.w, xr[i].w, a.w);
            }
            d[o] = c0s[o] + (a.x + a.y) + (a.z + a.w);
        }
    }
    __syncthreads();
    if (act) { for (int j = 0; j < 25; j++) xs[t * 28 + j] = b[j]; }
    __syncthreads();
    for (int i = t; i < nvalid * 32; i += 256) {
        int nd = i >> 5, c = i & 31;
        if (c < 25) g_B1[(base + nd) * 32 + c] = xs[nd * 28 + c];
    }
    __syncthreads();
    if (act) { for (int o = 0; o < 16; o++) xs[t * 16 + o] = d[o]; }
    __syncthreads();
    for (int i = t; i < nvalid * 16; i += 256) g_D1[base * 16 + i] = xs[i];
}

// =================================================================
// kernel 2: conv1 — gather B1, stats, matvec -> h1 (smem only),
// fused ab2 -> B2/D2. Persistent grid, inline weight fold.
// =================================================================
__global__ void __launch_bounds__(256) conv1_kernel(
    const int* __restrict__ src,
    const float* __restrict__ w1_post, const float* __restrict__ w1_lin,
    const float* __restrict__ w2_pre, const float* __restrict__ b2_pre,
    const float* __restrict__ w2_post, const float* __restrict__ b2_post,
    const float* __restrict__ w2_lin,  const float* __restrict__ b2_lin)
{
    __shared__ __align__(16) float sW1[16 * 132];   // rows: [mean 0-24|pad|min 32-|max 64-|std 96-]
    __shared__ __align__(16) float sagg[8][128];
    __shared__ __align__(16) float4 sWB[4 * 32];    // fused-ab2 weights: [i4][lane]
    __shared__ __align__(16) float sh1[8][16];
    __shared__ float pa[16 * 100];
    __shared__ float p92[8 * 16];
    __shared__ float wa2[8 * 16];
    __shared__ float c2m[8 * 16];
    __shared__ float c02s[8];

    int t = threadIdx.x;
    // ---- fold layer1 W ----
    for (int i = t; i < 16 * 100; i += 256) {
        int k = i / 100, j = i % 100;
        pa[i] = w1_post[k * 300 + j] + w1_post[k * 300 + 100 + j] + w1_post[k * 300 + 200 + j];
    }
    for (int i = t; i < 16 * 132; i += 256) sW1[i] = 0.f;
    for (int i = t; i < 8 * 16; i += 256) {
        int k = i / 16, jj = i % 16;
        const float* pr = w2_post + k * 192;
        p92[i] = pr[jj] + pr[16 + jj] + pr[32 + jj]
               + pr[64 + jj] + pr[80 + jj] + pr[96 + jj]
               + pr[128 + jj] + pr[144 + jj] + pr[160 + jj];
    }
    __syncthreads();
    for (int i = t; i < 16 * 100; i += 256) {
        int o = i / 100, j = i % 100;
        float s = 0.f;
        for (int k = 0; k < 16; k++) s = fmaf(w1_lin[o * 16 + k], pa[k * 100 + j], s);
        sW1[o * 132 + (j / 25) * 32 + (j % 25)] = s;
    }
    for (int i = t; i < 8 * 16; i += 256) {
        int o = i / 16, jj = i % 16;
        float s = 0.f;
        for (int k = 0; k < 8; k++) s = fmaf(w2_lin[o * 8 + k], p92[k * 16 + jj], s);
        wa2[i] = s;
    }
    __syncthreads();
    for (int i = t; i < 8 * 16; i += 256) {
        int o = i / 16, ii = i % 16;
        float s = 0.f;
        for (int j = 0; j < 16; j++) s = fmaf(wa2[o * 16 + j], w2_pre[j * 32 + ii], s);
        c2m[i] = s;
    }
    if (t < 8) {
        float s = b2_lin[t];
        for (int k = 0; k < 8; k++) s = fmaf(w2_lin[t * 8 + k], b2_post[k], s);
        for (int j = 0; j < 16; j++) s = fmaf(wa2[t * 16 + j], b2_pre[j], s);
        c02s[t] = s;
    }
    for (int i = t; i < 8 * 128; i += 256) ((float*)sagg)[i] = 0.f;
    __syncthreads();
    for (int i = t; i < 4 * 32; i += 256) {
        int i4 = i / 32, l = i % 32;
        float4 v = make_float4(0.f, 0.f, 0.f, 0.f);
        if (l < 16) {          // B2 weights: w2_pre src half, transposed per i4
            v.x = w2_pre[l * 32 + 16 + i4 * 4 + 0];
            v.y = w2_pre[l * 32 + 16 + i4 * 4 + 1];
            v.z = w2_pre[l * 32 + 16 + i4 * 4 + 2];
            v.w = w2_pre[l * 32 + 16 + i4 * 4 + 3];
        } else if (l < 24) {   // D2 weights: C2
            int o = l - 16;
            v.x = c2m[o * 16 + i4 * 4 + 0];
            v.y = c2m[o * 16 + i4 * 4 + 1];
            v.z = c2m[o * 16 + i4 * 4 + 2];
            v.w = c2m[o * 16 + i4 * 4 + 3];
        }
        sWB[i] = v;
    }
    __syncthreads();

    int w = t >> 5, lane = t & 31;
    for (int grp = blockIdx.x; grp < NN / 8; grp += gridDim.x) {
        int n = grp * 8 + w;
        int sv = __ldg(&src[n * 16 + (lane & 15)]);
        float sum = 0.f, sq = 0.f, mn = 1e30f, mx = -1e30f;
#pragma unroll
        for (int e = 0; e < 16; e++) {
            int s = __shfl_sync(0xffffffffu, sv, e);
            float bv = __ldg(&g_B1[s * 32 + lane]);   // lanes 25-31 read junk, unused
            sum += bv; sq = fmaf(bv, bv, sq);
            mn = fminf(mn, bv); mx = fmaxf(mx, bv);
        }
        if (lane < 25) {
            float mean = sum * (1.f / 16.f), m2 = sq * (1.f / 16.f);
            float st = sqrtf(fmaxf(m2 - mean * mean, 0.f) + EPS);
            sagg[w][lane]      = mean;
            sagg[w][32 + lane] = mn;
            sagg[w][64 + lane] = mx;
            sagg[w][96 + lane] = st;
        }
        __syncwarp();
        // matvec: 16 outputs x 2 column halves
        {
            int o = lane & 15, hf = lane >> 4;
            const float4* wr = (const float4*)&sW1[o * 132 + hf * 64];
            const float4* ar = (const float4*)&sagg[w][hf * 64];
            float4 a4 = make_float4(0.f, 0.f, 0.f, 0.f);
#pragma unroll
            for (int j = 0; j < 16; j++) {
                float4 wv = wr[j], av = ar[j];
                a4.x = fmaf(wv.x, av.x, a4.x); a4.y = fmaf(wv.y, av.y, a4.y);
                a4.z = fmaf(wv.z, av.z, a4.z); a4.w = fmaf(wv.w, av.w, a4.w);
            }
            float p = (a4.x + a4.y) + (a4.z + a4.w);
            p += __shfl_xor_sync(0xffffffffu, p, 16);
            if (lane < 16) {
                float h = fmaxf(p + __ldg(&g_D1[n * 16 + lane]), 0.f);
                sh1[w][lane] = h;
            }
        }
        __syncwarp();
        // fused ab2: lanes 0-15 -> B2, lanes 16-23 -> D2
        {
            float acc = (lane >= 16 && lane < 24) ? c02s[lane - 16] : 0.f;
            const float4* h4 = (const float4*)&sh1[w][0];
#pragma unroll
            for (int i4 = 0; i4 < 4; i4++) {
                float4 hv = h4[i4];
                float4 wv = sWB[i4 * 32 + lane];
                acc = fmaf(wv.x, hv.x, acc); acc = fmaf(wv.y, hv.y, acc);
                acc = fmaf(wv.z, hv.z, acc); acc = fmaf(wv.w, hv.w, acc);
            }
            if (lane < 16)      g_B2[n * 16 + lane] = acc;
            else if (lane < 24) g_D2[n * 8 + lane - 16] = acc;
        }
        __syncwarp();
    }
}

// =================================================================
// kernel 3: conv2 — 2 nodes/warp; gather B2, stats, matvec, relu,
// fused global pooling via atomicAdd. Persistent, inline fold.
// =================================================================
__global__ void __launch_bounds__(256) conv2_kernel(
    const int* __restrict__ src,
    const float* __restrict__ w2_post, const float* __restrict__ w2_lin)
{
    __shared__ __align__(16) float sW2[8 * 72];     // rows 64 cols [mean|min|max|std], stride 72
    __shared__ __align__(16) float sagg[8][2][64];
    __shared__ float pa[8 * 64];

    int t = threadIdx.x;
    for (int i = t; i < 8 * 64; i += 256) {
        int k = i / 64, j = i % 64;
        pa[i] = w2_post[k * 192 + j] + w2_post[k * 192 + 64 + j] + w2_post[k * 192 + 128 + j];
    }
    __syncthreads();
    for (int i = t; i < 8 * 64; i += 256) {
        int o = i / 64, j = i % 64;
        float s = 0.f;
        for (int k = 0; k < 8; k++) s = fmaf(w2_lin[o * 8 + k], pa[k * 64 + j], s);
        sW2[o * 72 + j] = s;
    }
    __syncthreads();

    int w = t >> 5, lane = t & 31;
    for (int grp = blockIdx.x; grp < NN / 16; grp += gridDim.x) {
        int nA = (grp * 8 + w) * 2;                 // this warp: nodes nA, nA+1
        int sv = __ldg(&src[nA * 16 + lane]);       // 32 contiguous edge srcs = both nodes
        float sum = 0.f, sq = 0.f, mn = 1e30f, mx = -1e30f;
#pragma unroll
        for (int e = 0; e < 16; e++) {
            int s = __shfl_sync(0xffffffffu, sv, e | (lane & 16));
            float bv = __ldg(&g_B2[s * 16 + (lane & 15)]);
            sum += bv; sq = fmaf(bv, bv, sq);
            mn = fminf(mn, bv); mx = fmaxf(mx, bv);
        }
        {
            float mean = sum * (1.f / 16.f), m2 = sq * (1.f / 16.f);
            float st = sqrtf(fmaxf(m2 - mean * mean, 0.f) + EPS);
            int nd = lane >> 4, f = lane & 15;
            sagg[w][nd][f]      = mean;
            sagg[w][nd][16 + f] = mn;
            sagg[w][nd][32 + f] = mx;
            sagg[w][nd][48 + f] = st;
        }
        __syncwarp();
        {
            int node = lane >> 4, o = (lane >> 1) & 7, hf = lane & 1;
            const float4* wr = (const float4*)&sW2[o * 72 + hf * 32];
            const float4* ar = (const float4*)&sagg[w][node][hf * 32];
            float4 a4 = make_float4(0.f, 0.f, 0.f, 0.f);
#pragma unroll
            for (int j = 0; j < 8; j++) {
                float4 wv = wr[j], av = ar[j];
                a4.x = fmaf(wv.x, av.x, a4.x); a4.y = fmaf(wv.y, av.y, a4.y);
                a4.z = fmaf(wv.z, av.z, a4.z); a4.w = fmaf(wv.w, av.w, a4.w);
            }
            float p = (a4.x + a4.y) + (a4.z + a4.w);
            p += __shfl_xor_sync(0xffffffffu, p, 1);
            if (hf == 0) {
                int n2 = nA + node;
                float h = fmaxf(p + __ldg(&g_D2[n2 * 8 + o]), 0.f);
                atomicAdd(&g_pooled[(n2 / NPG) * 8 + o], h);
            }
        }
        __syncwarp();
    }
}

// =================================================================
// kernel 4: FC + log_softmax per graph
// =================================================================
__global__ void final_kernel(const float* __restrict__ fc_w,
                             const float* __restrict__ fc_b,
                             float* __restrict__ out)
{
    int g = blockIdx.x * 256 + threadIdx.x;
    if (g >= GG) return;
    float l0 = fc_b[0], l1 = fc_b[1];
#pragma unroll
    for (int j = 0; j < 8; j++) {
        float p = g_pooled[g * 8 + j];
        l0 = fmaf(p, fc_w[j], l0);
        l1 = fmaf(p, fc_w[8 + j], l1);
    }
    float m = fmaxf(l0, l1);
    float lse = m + logf(expf(l0 - m) + expf(l1 - m));
    out[g * 2 + 0] = l0 - lse;
    out[g * 2 + 1] = l1 - lse;
}

// ---------------- launch ----------------
extern "C" void kernel_launch(void* const* d_in, const int* in_sizes, int n_in,
                              void* d_out, int out_size)
{
    const float* x       = (const float*)d_in[0];
    const int*   src     = (const int*)d_in[1];
    const float* w1_pre  = (const float*)d_in[3];
    const float* b1_pre  = (const float*)d_in[4];
    const float* w1_post = (const float*)d_in[5];
    const float* b1_post = (const float*)d_in[6];
    const float* w1_lin  = (const float*)d_in[7];
    const float* b1_lin  = (const float*)d_in[8];
    const float* w2_pre  = (const float*)d_in[9];
    const float* b2_pre  = (const float*)d_in[10];
    const float* w2_post = (const float*)d_in[11];
    const float* b2_post = (const float*)d_in[12];
    const float* w2_lin  = (const float*)d_in[13];
    const float* b2_lin  = (const float*)d_in[14];
    const float* fc_w    = (const float*)d_in[15];
    const float* fc_b    = (const float*)d_in[16];
    float* out = (float*)d_out;

    ab1_kernel<<<(NN + 255) / 256, 256>>>(x, w1_pre, b1_pre, w1_post, b1_post, w1_lin, b1_lin);
    conv1_kernel<<<1184, 256>>>(src, w1_post, w1_lin,
                                w2_pre, b2_pre, w2_post, b2_post, w2_lin, b2_lin);
    conv2_kernel<<<1184, 256>>>(src, w2_post, w2_lin);
    final_kernel<<<(GG + 255) / 256, 256>>>(fc_w, fc_b, out);
}